// round 9
// baseline (speedup 1.0000x reference)
#include <cuda_runtime.h>
#include <cuda_fp16.h>
#include <cstdint>

#define BB   8
#define SS   4096
#define DIN  512
#define DD   256

// ---------------------------------------------------------------------------
// Global scratch (static __device__ arrays: no allocation)
// ---------------------------------------------------------------------------
__device__ __half gx[BB * SS * DIN];
__device__ __half gWq[DIN * DD], gWk[DIN * DD], gWv[DIN * DD];
__device__ __half gQ[BB * SS * DD], gK[BB * SS * DD], gV[BB * SS * DD];
__device__ float gOp[3][BB * SS * DD];   // O partials for k-quarters 0..2
__device__ float gLp[3][BB * SS];        // l partials
__device__ int   projDone[BB];           // per-batch proj completion counters
__device__ int   tileDone[256];          // per-qtile flash partial counters

// ---------------------------------------------------------------------------
// helpers
// ---------------------------------------------------------------------------
__device__ __forceinline__ uint32_t smem_u32(const void* p) {
    uint32_t a;
    asm("{ .reg .u64 t; cvta.to.shared.u64 t, %1; cvt.u32.u64 %0, t; }"
        : "=r"(a) : "l"(p));
    return a;
}
__device__ __forceinline__ void ldsm4(uint32_t a, uint32_t r[4]) {
    asm volatile("ldmatrix.sync.aligned.m8n8.x4.shared.b16 {%0,%1,%2,%3}, [%4];"
        : "=r"(r[0]), "=r"(r[1]), "=r"(r[2]), "=r"(r[3]) : "r"(a));
}
__device__ __forceinline__ void ldsm4t(uint32_t a, uint32_t r[4]) {
    asm volatile("ldmatrix.sync.aligned.m8n8.x4.trans.shared.b16 {%0,%1,%2,%3}, [%4];"
        : "=r"(r[0]), "=r"(r[1]), "=r"(r[2]), "=r"(r[3]) : "r"(a));
}
__device__ __forceinline__ void mma_f16(float c[4], const uint32_t a[4],
                                        uint32_t b0, uint32_t b1) {
    asm volatile(
        "mma.sync.aligned.m16n8k16.row.col.f32.f16.f16.f32 "
        "{%0,%1,%2,%3}, {%4,%5,%6,%7}, {%8,%9}, {%0,%1,%2,%3};"
        : "+f"(c[0]), "+f"(c[1]), "+f"(c[2]), "+f"(c[3])
        : "r"(a[0]), "r"(a[1]), "r"(a[2]), "r"(a[3]), "r"(b0), "r"(b1));
}
__device__ __forceinline__ float ex2(float x) {
    float r;
    asm("ex2.approx.f32 %0, %1;" : "=f"(r) : "f"(x));
    return r;
}
__device__ __forceinline__ uint32_t h2u(__half2 h) {
    return *reinterpret_cast<uint32_t*>(&h);
}
__device__ __forceinline__ void sts32(uint32_t a, uint32_t v) {
    asm volatile("st.shared.b32 [%0], %1;" :: "r"(a), "r"(v));
}
__device__ __forceinline__ void cpa16(uint32_t s, const void* g) {
    asm volatile("cp.async.cg.shared.global [%0], [%1], 16;" :: "r"(s), "l"(g));
}
#define CP_COMMIT() asm volatile("cp.async.commit_group;" ::: "memory")
#define CP_WAIT1()  asm volatile("cp.async.wait_group 1;" ::: "memory")
#define CP_WAIT0()  asm volatile("cp.async.wait_group 0;" ::: "memory")

__device__ __forceinline__ void spin_on(volatile int* ctr, int target) {
    while (*ctr < target) __nanosleep(128);
}

// ---------------------------------------------------------------------------
// Kernel 0: convert x + weights fp32->fp16, zero the flow counters.
// ---------------------------------------------------------------------------
#define NX4 (BB * SS * DIN / 4)
#define NW4 (DIN * DD / 4)

__global__ void convert_all(const float* __restrict__ x,
                            const float* __restrict__ Wq,
                            const float* __restrict__ Wk,
                            const float* __restrict__ Wv)
{
    if (blockIdx.x == 0) {
        int t = threadIdx.x;
        tileDone[t] = 0;
        if (t < BB) projDone[t] = 0;
    }
    int i = blockIdx.x * blockDim.x + threadIdx.x;
    const float* src;
    __half* dst;
    int idx;
    if (i < NX4) {
        src = x; dst = gx; idx = i;
    } else {
        int j = i - NX4;
        if (j >= 3 * NW4) return;
        int w = j / NW4;
        idx = j - w * NW4;
        src = (w == 0) ? Wq : (w == 1) ? Wk : Wv;
        dst = (w == 0) ? gWq : (w == 1) ? gWk : gWv;
    }
    float4 v = ((const float4*)src)[idx];
    __half2 a = __floats2half2_rn(v.x, v.y);
    __half2 b = __floats2half2_rn(v.z, v.w);
    ((uint2*)dst)[idx] = make_uint2(h2u(a), h2u(b));
}

// ---------------------------------------------------------------------------
// Fused mega-kernel. grid = 1792 CTAs, 256 thr.
//   bid [0,768):    proj units (b=bid/96, yb, xt)
//   bid [768,1792): flash units: kq=fid/256, tile=fid%256
// Flash smem: Q[0,64K) | K/V stage st at 64K+st*64K (K 32K + V 32K) |
//             P 128x128B at 192K | Lbuf float[128] at 208K.
// QK: 8 warps = 4 row-quarters x 2 key-halves. PV: 8 warps split D (32 cols).
// P goes through smem (fp16 swizzled); l partials merged via smem atomicAdd.
// ---------------------------------------------------------------------------
#define MEGA_SMEM 213504
#define P_OFF     196608
#define LBUF_OFF  212992
// proj smem layout
#define PJ_W0     32768
#define PJ_XSTG   16384
#define PJ_WSTG   32768

__device__ __forceinline__ void proj_issue(uint32_t sb, int st, int kb,
                                           const __half* xg, const __half* Wg,
                                           int tid)
{
    #pragma unroll
    for (int t = 0; t < 4; t++) {
        int idx = tid + t * 256;
        int r = idx >> 3, c = idx & 7;
        cpa16(sb + st * PJ_XSTG + (uint32_t)(r * 128 + ((c ^ (r & 7)) << 4)),
              xg + (size_t)r * DIN + kb * 64 + c * 8);
    }
    #pragma unroll
    for (int t = 0; t < 8; t++) {
        int idx = tid + t * 256;
        int r = idx >> 5, c = idx & 31;
        cpa16(sb + PJ_W0 + st * PJ_WSTG + (uint32_t)(r * 512 + ((c ^ (r & 7)) << 4)),
              Wg + (size_t)(kb * 64 + r) * DD + c * 8);
    }
    CP_COMMIT();
}

__device__ __forceinline__ void kv_issue_nc(uint32_t sb, int st,
                                            const __half* Kg, const __half* Vg,
                                            int tid)
{
    const uint32_t kbase = sb + 65536 + st * 65536;
    #pragma unroll
    for (int t = 0; t < 8; t++) {
        int idx = tid + t * 256;
        int r = idx >> 5, c = idx & 31;
        uint32_t off = (uint32_t)(r * 512 + ((c ^ (r & 7)) << 4));
        cpa16(kbase + off,         Kg + (size_t)r * DD + c * 8);
        cpa16(kbase + 32768 + off, Vg + (size_t)r * DD + c * 8);
    }
}

__global__ __launch_bounds__(256, 1) void mega(
    const float* __restrict__ bq, const float* __restrict__ bk,
    const float* __restrict__ bv, float* __restrict__ out)
{
    extern __shared__ char sm[];
    const uint32_t sb = smem_u32(sm);
    const int bid = blockIdx.x;
    const int tid = threadIdx.x;
    const int w   = tid >> 5;
    const int l   = tid & 31;
    const int grp = l >> 2, tid4 = l & 3;

    if (bid < 768) {
        // ==================== PROJ UNIT ====================
        const int bb = bid / 96;
        const int r96 = bid - bb * 96;
        const int yb = r96 >> 5;
        const int xt = r96 & 31;
        const int m0 = (bb * 32 + xt) * 128;

        const __half* W    = (yb == 0) ? gWq : (yb == 1) ? gWk : gWv;
        const float*  bias = (yb == 0) ? bq  : (yb == 1) ? bk  : bv;
        __half*       O    = (yb == 0) ? gQ  : (yb == 1) ? gK  : gV;
        const float scl = (yb == 0) ? 0.09014205f : 1.0f;  // log2(e)/16

        float o[32][4];
        #pragma unroll
        for (int i = 0; i < 32; i++)
            #pragma unroll
            for (int j = 0; j < 4; j++) o[i][j] = 0.f;

        const int rA  = w * 16 + (l & 15);
        const int cA  = l >> 4;
        const int rxA = rA & 7;
        const int rWb = (l & 7) + ((l >> 3) & 1) * 8;
        const int cW  = l >> 4;
        const int rxW = l & 7;

        const __half* xg = gx + (size_t)m0 * DIN;
        proj_issue(sb, 0, 0, xg, W, tid);

        #pragma unroll 1
        for (int kb = 0; kb < 8; kb++) {
            const int st = kb & 1;
            if (kb + 1 < 8) {
                proj_issue(sb, st ^ 1, kb + 1, xg, W, tid);
                CP_WAIT1();
            } else {
                CP_WAIT0();
            }
            __syncthreads();

            const uint32_t sX = sb + st * PJ_XSTG;
            const uint32_t sW = sb + PJ_W0 + st * PJ_WSTG;

            #pragma unroll
            for (int ks = 0; ks < 4; ks++) {
                uint32_t a[4];
                ldsm4(sX + rA * 128 + (((2 * ks + cA) ^ rxA) << 4), a);
                #pragma unroll
                for (int g = 0; g < 16; g++) {
                    uint32_t bfr[4];
                    ldsm4t(sW + (ks * 16 + rWb) * 512 + (((2 * g + cW) ^ rxW) << 4), bfr);
                    mma_f16(o[2 * g],     a, bfr[0], bfr[1]);
                    mma_f16(o[2 * g + 1], a, bfr[2], bfr[3]);
                }
            }
            __syncthreads();
        }

        const int r0 = m0 + w * 16 + grp;
        #pragma unroll
        for (int nf = 0; nf < 32; nf++) {
            int col = nf * 8 + tid4 * 2;
            float b0 = bias[col], b1 = bias[col + 1];
            __half2 h0 = __floats2half2_rn((o[nf][0] + b0) * scl, (o[nf][1] + b1) * scl);
            __half2 h1 = __floats2half2_rn((o[nf][2] + b0) * scl, (o[nf][3] + b1) * scl);
            *(uint32_t*)(O + (size_t)r0 * DD + col)       = h2u(h0);
            *(uint32_t*)(O + (size_t)(r0 + 8) * DD + col) = h2u(h1);
        }
        __threadfence();
        __syncthreads();
        if (tid == 0) atomicAdd(&projDone[bb], 1);
        return;
    }

    // ==================== FLASH UNIT (one k-quarter of one q-tile) ====
    const int fid  = bid - 768;
    const int kq   = fid >> 8;         // 0..3
    const int tile = fid & 255;
    const int b    = tile >> 5;
    const int q0   = (tile & 31) << 7;
    const size_t qbase = (size_t)b * SS + q0;
    const size_t kvb   = (size_t)b * SS;
    const int kt0 = kq * 16;

    float* LbufF = (float*)(sm + (LBUF_OFF - (sb - sb)));  // placeholder
    LbufF = (float*)(sm + LBUF_OFF);
    if (tid < 128) LbufF[tid] = 0.f;

    if (tid == 0) {
        spin_on(projDone + b, 96);
        __threadfence();
    }
    __syncthreads();

    // prologue: KV tile kt0 + Q tile in one cp.async group
    kv_issue_nc(sb, 0, gK + (kvb + kt0 * 64) * DD, gV + (kvb + kt0 * 64) * DD, tid);
    #pragma unroll
    for (int t = 0; t < 16; t++) {
        int idx = tid + t * 256;
        int r = idx >> 5, c = idx & 31;
        cpa16(sb + (uint32_t)(r * 512 + ((c ^ (r & 7)) << 4)),
              gQ + (qbase + r) * DD + c * 8);
    }
    CP_COMMIT();

    float o[32][4];   // [m*4+n]: rows 16m+grp(+8), cols 32w+8n+tid4*2
    #pragma unroll
    for (int i = 0; i < 32; i++)
        #pragma unroll
        for (int j = 0; j < 4; j++) o[i][j] = 0.f;
    float lsum[4] = {0.f, 0.f, 0.f, 0.f};   // [i*2+half]

    const int mq = w & 3;          // QK row quarter
    const int kh = w >> 2;         // QK key half
    const int rQ = l & 15, cQ = l >> 4;
    const int rxQ = rQ & 7;
    const int rK = ((l >> 4) << 3) + (l & 7), cK = (l >> 3) & 1;
    const int rxK = rK & 7;
    const int rV = (l & 7) + ((l >> 3) & 1) * 8, cV = l >> 4;
    const int rxV = rV & 7;
    const uint32_t qrow0 = sb + (32 * mq + rQ) * 512;
    const uint32_t qrow1 = sb + (32 * mq + 16 + rQ) * 512;
    const uint32_t pP = sb + P_OFF;

    #pragma unroll 1
    for (int kt = 0; kt < 16; kt++) {
        const int st = kt & 1;
        if (kt + 1 < 16) {
            kv_issue_nc(sb, st ^ 1, gK + (kvb + (kt0 + kt + 1) * 64) * DD,
                        gV + (kvb + (kt0 + kt + 1) * 64) * DD, tid);
            CP_COMMIT();
            CP_WAIT1();
        } else {
            CP_WAIT0();
        }
        __syncthreads();

        const uint32_t sKb = sb + 65536 + st * 65536;
        const uint32_t sVb = sKb + 32768;

        // ---- S = Q K^T: warp = 32 rows (quarter mq) x 32 keys (half kh) ----
        float s[8][4];   // [i*4 + j]
        #pragma unroll
        for (int i = 0; i < 8; i++)
            #pragma unroll
            for (int j = 0; j < 4; j++) s[i][j] = 0.f;

        #pragma unroll
        for (int ks = 0; ks < 16; ks++) {
            uint32_t a0[4], a1[4];
            ldsm4(qrow0 + (((2 * ks + cQ) ^ rxQ) << 4), a0);
            ldsm4(qrow1 + (((2 * ks + cQ) ^ rxQ) << 4), a1);
            #pragma unroll
            for (int h = 0; h < 2; h++) {
                uint32_t kf[4];
                ldsm4(sKb + (32 * kh + 16 * h + rK) * 512
                          + (((2 * ks + cK) ^ rxK) << 4), kf);
                mma_f16(s[2 * h],         a0, kf[0], kf[1]);
                mma_f16(s[2 * h + 1],     a0, kf[2], kf[3]);
                mma_f16(s[4 + 2 * h],     a1, kf[0], kf[1]);
                mma_f16(s[4 + 2 * h + 1], a1, kf[2], kf[3]);
            }
        }

        // ---- softmax: exp2 + fp16 P -> smem (swizzled); accumulate l ----
        #pragma unroll
        for (int i = 0; i < 2; i++) {
            const int row0 = 32 * mq + 16 * i + grp;
            const uint32_t rb0 = pP + row0 * 128;
            const uint32_t rb1 = pP + (row0 + 8) * 128;
            #pragma unroll
            for (int j = 0; j < 4; j++) {
                float* c = s[i * 4 + j];
                float e0 = ex2(c[0]), e1 = ex2(c[1]);
                float e2 = ex2(c[2]), e3 = ex2(c[3]);
                lsum[i * 2]     += e0 + e1;
                lsum[i * 2 + 1] += e2 + e3;
                const int col = 32 * kh + 8 * j + tid4 * 2;
                const uint32_t coff = (uint32_t)((((col >> 3) ^ grp) << 4) + (col & 7) * 2);
                sts32(rb0 + coff, h2u(__floats2half2_rn(e0, e1)));
                sts32(rb1 + coff, h2u(__floats2half2_rn(e2, e3)));
            }
        }
        __syncthreads();   // P ready for all warps

        // ---- O += P V: warp = all 128 rows x 32 d-cols [32w, 32w+32) ----
        #pragma unroll
        for (int kb = 0; kb < 4; kb++) {
            uint32_t vb0[4], vb1[4];
            const uint32_t vrow = sVb + (16 * kb + rV) * 512;
            ldsm4t(vrow + (((4 * w + cV) ^ rxV) << 4), vb0);
            ldsm4t(vrow + (((4 * w + 2 + cV) ^ rxV) << 4), vb1);
            #pragma unroll
            for (int m = 0; m < 8; m++) {
                uint32_t pa[4];
                ldsm4(pP + (16 * m + rQ) * 128 + (((2 * kb + cQ) ^ rxQ) << 4), pa);
                mma_f16(o[m * 4 + 0], pa, vb0[0], vb0[1]);
                mma_f16(o[m * 4 + 1], pa, vb0[2], vb0[3]);
                mma_f16(o[m * 4 + 2], pa, vb1[0], vb1[1]);
                mma_f16(o[m * 4 + 3], pa, vb1[2], vb1[3]);
            }
        }
        __syncthreads();   // protect K/V stage + P before next tile
    }

    // ---- merge l partials across quads and key-half warps ----
    #pragma unroll
    for (int t = 0; t < 4; t++) {
        lsum[t] += __shfl_xor_sync(0xffffffffu, lsum[t], 1);
        lsum[t] += __shfl_xor_sync(0xffffffffu, lsum[t], 2);
    }
    if (tid4 == 0) {
        atomicAdd(LbufF + 32 * mq + grp,      lsum[0]);
        atomicAdd(LbufF + 32 * mq + grp + 8,  lsum[1]);
        atomicAdd(LbufF + 32 * mq + 16 + grp, lsum[2]);
        atomicAdd(LbufF + 32 * mq + 24 + grp, lsum[3]);
    }
    __syncthreads();

    if (kq < 3) {
        if (tid < 128) gLp[kq][qbase + tid] = LbufF[tid];
        #pragma unroll
        for (int m = 0; m < 8; m++) {
            const size_t row = qbase + 16 * m + grp;
            #pragma unroll
            for (int n = 0; n < 4; n++) {
                const int col = 32 * w + 8 * n + tid4 * 2;
                *(float2*)&gOp[kq][row * DD + col] =
                    make_float2(o[m * 4 + n][0], o[m * 4 + n][1]);
                *(float2*)&gOp[kq][(row + 8) * DD + col] =
                    make_float2(o[m * 4 + n][2], o[m * 4 + n][3]);
            }
        }
        __threadfence();
        __syncthreads();
        if (tid == 0) atomicAdd(&tileDone[tile], 1);
    } else {
        if (tid == 0) {
            spin_on(tileDone + tile, 3);
            __threadfence();
        }
        __syncthreads();

        #pragma unroll 1
        for (int m = 0; m < 8; m++) {
            const int lr = 16 * m + grp;
            const size_t row = qbase + lr;
            float l0 = LbufF[lr]     + gLp[0][row]     + gLp[1][row]     + gLp[2][row];
            float l1 = LbufF[lr + 8] + gLp[0][row + 8] + gLp[1][row + 8] + gLp[2][row + 8];
            const float inv0 = 1.f / l0, inv1 = 1.f / l1;
            #pragma unroll
            for (int n = 0; n < 4; n++) {
                const int col = 32 * w + 8 * n + tid4 * 2;
                const size_t i0 = row * DD + col;
                const size_t i1 = (row + 8) * DD + col;
                float2 a = make_float2(o[m * 4 + n][0], o[m * 4 + n][1]);
                float2 c = make_float2(o[m * 4 + n][2], o[m * 4 + n][3]);
                #pragma unroll
                for (int k = 0; k < 3; k++) {
                    float2 pa = *(const float2*)&gOp[k][i0];
                    float2 pc = *(const float2*)&gOp[k][i1];
                    a.x += pa.x; a.y += pa.y;
                    c.x += pc.x; c.y += pc.y;
                }
                *(float2*)(out + i0) = make_float2(a.x * inv0, a.y * inv0);
                *(float2*)(out + i1) = make_float2(c.x * inv1, c.y * inv1);
            }
        }
    }
}

// ---------------------------------------------------------------------------
extern "C" void kernel_launch(void* const* d_in, const int* in_sizes, int n_in,
                              void* d_out, int out_size)
{
    const float* x  = (const float*)d_in[0];
    const float* Wq = (const float*)d_in[1];
    const float* bq = (const float*)d_in[2];
    const float* Wk = (const float*)d_in[3];
    const float* bk = (const float*)d_in[4];
    const float* Wv = (const float*)d_in[5];
    const float* bv = (const float*)d_in[6];
    float* out = (float*)d_out;

    cudaFuncSetAttribute(mega, cudaFuncAttributeMaxDynamicSharedMemorySize,
                         MEGA_SMEM);

    convert_all<<<(NX4 + 3 * NW4 + 255) / 256, 256>>>(x, Wq, Wk, Wv);
    mega<<<768 + 1024, 256, MEGA_SMEM>>>(bq, bk, bv, out);
}

// round 10
// speedup vs baseline: 1.0212x; 1.0212x over previous
#include <cuda_runtime.h>
#include <cuda_fp16.h>
#include <cstdint>

#define BB   8
#define SS   4096
#define DIN  512
#define DD   256

// ---------------------------------------------------------------------------
// Global scratch (static __device__ arrays: no allocation)
// ---------------------------------------------------------------------------
__device__ __half gx[BB * SS * DIN];
__device__ __half gWq[DIN * DD], gWk[DIN * DD], gWv[DIN * DD];
__device__ __half gQ[BB * SS * DD], gK[BB * SS * DD], gV[BB * SS * DD];
__device__ float gOp[3][BB * SS * DD];   // O partials for k-quarters 0..2
__device__ float gLp[3][BB * SS];        // l partials
__device__ int   projDone[BB];           // per-batch proj completion counters
__device__ int   tileDone[256];          // per-qtile flash partial counters

// ---------------------------------------------------------------------------
// helpers
// ---------------------------------------------------------------------------
__device__ __forceinline__ uint32_t smem_u32(const void* p) {
    uint32_t a;
    asm("{ .reg .u64 t; cvta.to.shared.u64 t, %1; cvt.u32.u64 %0, t; }"
        : "=r"(a) : "l"(p));
    return a;
}
__device__ __forceinline__ void ldsm4(uint32_t a, uint32_t r[4]) {
    asm volatile("ldmatrix.sync.aligned.m8n8.x4.shared.b16 {%0,%1,%2,%3}, [%4];"
        : "=r"(r[0]), "=r"(r[1]), "=r"(r[2]), "=r"(r[3]) : "r"(a));
}
__device__ __forceinline__ void ldsm4t(uint32_t a, uint32_t r[4]) {
    asm volatile("ldmatrix.sync.aligned.m8n8.x4.trans.shared.b16 {%0,%1,%2,%3}, [%4];"
        : "=r"(r[0]), "=r"(r[1]), "=r"(r[2]), "=r"(r[3]) : "r"(a));
}
__device__ __forceinline__ void mma_f16(float c[4], const uint32_t a[4],
                                        uint32_t b0, uint32_t b1) {
    asm volatile(
        "mma.sync.aligned.m16n8k16.row.col.f32.f16.f16.f32 "
        "{%0,%1,%2,%3}, {%4,%5,%6,%7}, {%8,%9}, {%0,%1,%2,%3};"
        : "+f"(c[0]), "+f"(c[1]), "+f"(c[2]), "+f"(c[3])
        : "r"(a[0]), "r"(a[1]), "r"(a[2]), "r"(a[3]), "r"(b0), "r"(b1));
}
__device__ __forceinline__ float ex2(float x) {
    float r;
    asm("ex2.approx.f32 %0, %1;" : "=f"(r) : "f"(x));
    return r;
}
__device__ __forceinline__ uint32_t h2u(__half2 h) {
    return *reinterpret_cast<uint32_t*>(&h);
}
__device__ __forceinline__ void sts32(uint32_t a, uint32_t v) {
    asm volatile("st.shared.b32 [%0], %1;" :: "r"(a), "r"(v));
}
__device__ __forceinline__ void cpa16(uint32_t s, const void* g) {
    asm volatile("cp.async.cg.shared.global [%0], [%1], 16;" :: "r"(s), "l"(g));
}
#define CP_COMMIT() asm volatile("cp.async.commit_group;" ::: "memory")
#define CP_WAIT1()  asm volatile("cp.async.wait_group 1;" ::: "memory")
#define CP_WAIT0()  asm volatile("cp.async.wait_group 0;" ::: "memory")

__device__ __forceinline__ void spin_on(volatile int* ctr, int target) {
    while (*ctr < target) __nanosleep(128);
}

// ---------------------------------------------------------------------------
// Kernel 0: convert x + weights fp32->fp16, zero the flow counters.
// ---------------------------------------------------------------------------
#define NX4 (BB * SS * DIN / 4)
#define NW4 (DIN * DD / 4)

__global__ void convert_all(const float* __restrict__ x,
                            const float* __restrict__ Wq,
                            const float* __restrict__ Wk,
                            const float* __restrict__ Wv)
{
    if (blockIdx.x == 0) {
        int t = threadIdx.x;
        tileDone[t] = 0;
        if (t < BB) projDone[t] = 0;
    }
    int i = blockIdx.x * blockDim.x + threadIdx.x;
    const float* src;
    __half* dst;
    int idx;
    if (i < NX4) {
        src = x; dst = gx; idx = i;
    } else {
        int j = i - NX4;
        if (j >= 3 * NW4) return;
        int w = j / NW4;
        idx = j - w * NW4;
        src = (w == 0) ? Wq : (w == 1) ? Wk : Wv;
        dst = (w == 0) ? gWq : (w == 1) ? gWk : gWv;
    }
    float4 v = ((const float4*)src)[idx];
    __half2 a = __floats2half2_rn(v.x, v.y);
    __half2 b = __floats2half2_rn(v.z, v.w);
    ((uint2*)dst)[idx] = make_uint2(h2u(a), h2u(b));
}

// ---------------------------------------------------------------------------
// Fused mega-kernel. grid = 1792 CTAs, 256 thr.
//   bid [0,768):    proj units (b=bid/96, yb, xt)
//   bid [768,1792): flash units: kq=fid/256, tile=fid%256
// Flash smem: Q[0,64K) | K/V stage st at 64K+st*64K | P 2 bufs x 4 pairs x 4KB
//             at 192K | Lbuf float[128] at 224K.
// QK: warp = 16 rows x 64 keys (as R8). P -> pair-shared smem (dbl-buffered).
// PV: warp pair splits D: warp = 32 rows x 128 cols (V dedup 8x -> 4x).
// Pair sync via named barrier (1+pair, 64 thr) — one per tile.
// ---------------------------------------------------------------------------
#define MEGA_SMEM 229888
#define P_OFF     196608
#define LBUF_OFF  229376
// proj smem layout
#define PJ_W0     32768
#define PJ_XSTG   16384
#define PJ_WSTG   32768

__device__ __forceinline__ void proj_issue(uint32_t sb, int st, int kb,
                                           const __half* xg, const __half* Wg,
                                           int tid)
{
    #pragma unroll
    for (int t = 0; t < 4; t++) {
        int idx = tid + t * 256;
        int r = idx >> 3, c = idx & 7;
        cpa16(sb + st * PJ_XSTG + (uint32_t)(r * 128 + ((c ^ (r & 7)) << 4)),
              xg + (size_t)r * DIN + kb * 64 + c * 8);
    }
    #pragma unroll
    for (int t = 0; t < 8; t++) {
        int idx = tid + t * 256;
        int r = idx >> 5, c = idx & 31;
        cpa16(sb + PJ_W0 + st * PJ_WSTG + (uint32_t)(r * 512 + ((c ^ (r & 7)) << 4)),
              Wg + (size_t)(kb * 64 + r) * DD + c * 8);
    }
    CP_COMMIT();
}

__device__ __forceinline__ void kv_issue_nc(uint32_t sb, int st,
                                            const __half* Kg, const __half* Vg,
                                            int tid)
{
    const uint32_t kbase = sb + 65536 + st * 65536;
    #pragma unroll
    for (int t = 0; t < 8; t++) {
        int idx = tid + t * 256;
        int r = idx >> 5, c = idx & 31;
        uint32_t off = (uint32_t)(r * 512 + ((c ^ (r & 7)) << 4));
        cpa16(kbase + off,         Kg + (size_t)r * DD + c * 8);
        cpa16(kbase + 32768 + off, Vg + (size_t)r * DD + c * 8);
    }
}

__global__ __launch_bounds__(256, 1) void mega(
    const float* __restrict__ bq, const float* __restrict__ bk,
    const float* __restrict__ bv, float* __restrict__ out)
{
    extern __shared__ char sm[];
    const uint32_t sb = smem_u32(sm);
    const int bid = blockIdx.x;
    const int tid = threadIdx.x;
    const int w   = tid >> 5;
    const int l   = tid & 31;
    const int grp = l >> 2, tid4 = l & 3;

    if (bid < 768) {
        // ==================== PROJ UNIT (unchanged from R8) ====================
        const int bb = bid / 96;
        const int r96 = bid - bb * 96;
        const int yb = r96 >> 5;
        const int xt = r96 & 31;
        const int m0 = (bb * 32 + xt) * 128;

        const __half* W    = (yb == 0) ? gWq : (yb == 1) ? gWk : gWv;
        const float*  bias = (yb == 0) ? bq  : (yb == 1) ? bk  : bv;
        __half*       O    = (yb == 0) ? gQ  : (yb == 1) ? gK  : gV;
        const float scl = (yb == 0) ? 0.09014205f : 1.0f;  // log2(e)/16

        float o[32][4];
        #pragma unroll
        for (int i = 0; i < 32; i++)
            #pragma unroll
            for (int j = 0; j < 4; j++) o[i][j] = 0.f;

        const int rA  = w * 16 + (l & 15);
        const int cA  = l >> 4;
        const int rxA = rA & 7;
        const int rWb = (l & 7) + ((l >> 3) & 1) * 8;
        const int cW  = l >> 4;
        const int rxW = l & 7;

        const __half* xg = gx + (size_t)m0 * DIN;
        proj_issue(sb, 0, 0, xg, W, tid);

        #pragma unroll 1
        for (int kb = 0; kb < 8; kb++) {
            const int st = kb & 1;
            if (kb + 1 < 8) {
                proj_issue(sb, st ^ 1, kb + 1, xg, W, tid);
                CP_WAIT1();
            } else {
                CP_WAIT0();
            }
            __syncthreads();

            const uint32_t sX = sb + st * PJ_XSTG;
            const uint32_t sW = sb + PJ_W0 + st * PJ_WSTG;

            #pragma unroll
            for (int ks = 0; ks < 4; ks++) {
                uint32_t a[4];
                ldsm4(sX + rA * 128 + (((2 * ks + cA) ^ rxA) << 4), a);
                #pragma unroll
                for (int g = 0; g < 16; g++) {
                    uint32_t bfr[4];
                    ldsm4t(sW + (ks * 16 + rWb) * 512 + (((2 * g + cW) ^ rxW) << 4), bfr);
                    mma_f16(o[2 * g],     a, bfr[0], bfr[1]);
                    mma_f16(o[2 * g + 1], a, bfr[2], bfr[3]);
                }
            }
            __syncthreads();
        }

        const int r0 = m0 + w * 16 + grp;
        #pragma unroll
        for (int nf = 0; nf < 32; nf++) {
            int col = nf * 8 + tid4 * 2;
            float b0 = bias[col], b1 = bias[col + 1];
            __half2 h0 = __floats2half2_rn((o[nf][0] + b0) * scl, (o[nf][1] + b1) * scl);
            __half2 h1 = __floats2half2_rn((o[nf][2] + b0) * scl, (o[nf][3] + b1) * scl);
            *(uint32_t*)(O + (size_t)r0 * DD + col)       = h2u(h0);
            *(uint32_t*)(O + (size_t)(r0 + 8) * DD + col) = h2u(h1);
        }
        __threadfence();
        __syncthreads();
        if (tid == 0) atomicAdd(&projDone[bb], 1);
        return;
    }

    // ==================== FLASH UNIT (one k-quarter of one q-tile) ====
    const int fid  = bid - 768;
    const int kq   = fid >> 8;         // 0..3
    const int tile = fid & 255;
    const int b    = tile >> 5;
    const int q0   = (tile & 31) << 7;
    const size_t qbase = (size_t)b * SS + q0;
    const size_t kvb   = (size_t)b * SS;
    const int kt0 = kq * 16;

    float* LbufF = (float*)(sm + LBUF_OFF);

    if (tid == 0) {
        spin_on(projDone + b, 96);
        __threadfence();
    }
    __syncthreads();

    // prologue: KV tile kt0 + Q tile in one cp.async group
    kv_issue_nc(sb, 0, gK + (kvb + kt0 * 64) * DD, gV + (kvb + kt0 * 64) * DD, tid);
    #pragma unroll
    for (int t = 0; t < 16; t++) {
        int idx = tid + t * 256;
        int r = idx >> 5, c = idx & 31;
        cpa16(sb + (uint32_t)(r * 512 + ((c ^ (r & 7)) << 4)),
              gQ + (qbase + r) * DD + c * 8);
    }
    CP_COMMIT();

    // O accum: warp (aP=w>>1, hP=w&1): rows [32aP,32aP+32) x cols [128hP,+128)
    // o[m*16+j]: rows 32aP+16m+grp(+8), cols 128hP+8j+tid4*2
    float o[32][4];
    #pragma unroll
    for (int i = 0; i < 32; i++)
        #pragma unroll
        for (int j = 0; j < 4; j++) o[i][j] = 0.f;
    float lsum0 = 0.f, lsum1 = 0.f;

    const int aP = w >> 1, hP = w & 1;
    const int rA  = w * 16 + (l & 15);
    const int cA  = l >> 4;
    const int rxA = rA & 7;
    const uint32_t qrow = sb + rA * 512;
    const int rK  = ((l >> 4) << 3) + (l & 7);
    const int cK  = (l >> 3) & 1;
    const int rP  = l & 15, cP = l >> 4;
    const int rxP = rP & 7;
    const int rV  = (l & 7) + ((l >> 3) & 1) * 8;
    const int cV  = l >> 4;
    const int rx  = l & 7;
    const int lr  = 16 * (w & 1) + grp;   // local P row within pair buffer

    #pragma unroll 1
    for (int kt = 0; kt < 16; kt++) {
        const int st = kt & 1;
        if (kt + 1 < 16) {
            kv_issue_nc(sb, st ^ 1, gK + (kvb + (kt0 + kt + 1) * 64) * DD,
                        gV + (kvb + (kt0 + kt + 1) * 64) * DD, tid);
            CP_COMMIT();
            CP_WAIT1();
        } else {
            CP_WAIT0();
        }
        __syncthreads();

        const uint32_t sKb = sb + 65536 + st * 65536;
        const uint32_t sVb = sKb + 32768;
        const uint32_t pbase = sb + P_OFF + st * 16384 + aP * 4096;

        // ---- S = Q K^T  (16 rows x 64 keys per warp — exactly R8) ----
        float s[8][4];
        #pragma unroll
        for (int i = 0; i < 8; i++)
            #pragma unroll
            for (int j = 0; j < 4; j++) s[i][j] = 0.f;

        #pragma unroll
        for (int ks = 0; ks < 16; ks++) {
            uint32_t a[4];
            ldsm4(qrow + (((2 * ks + cA) ^ rxA) << 4), a);
            #pragma unroll
            for (int h = 0; h < 4; h++) {
                uint32_t kh[4];
                ldsm4(sKb + (rK + h * 16) * 512 + (((2 * ks + cK) ^ rx) << 4), kh);
                mma_f16(s[2 * h],     a, kh[0], kh[1]);
                mma_f16(s[2 * h + 1], a, kh[2], kh[3]);
            }
        }

        // ---- softmax: exp2, accumulate l, write P to pair buffer ----
        #pragma unroll
        for (int kb = 0; kb < 4; kb++) {
            float e0 = ex2(s[2 * kb][0]),     e1 = ex2(s[2 * kb][1]);
            float e2 = ex2(s[2 * kb][2]),     e3 = ex2(s[2 * kb][3]);
            float e4 = ex2(s[2 * kb + 1][0]), e5 = ex2(s[2 * kb + 1][1]);
            float e6 = ex2(s[2 * kb + 1][2]), e7 = ex2(s[2 * kb + 1][3]);
            lsum0 += (e0 + e1) + (e4 + e5);
            lsum1 += (e2 + e3) + (e6 + e7);
            const int col0 = 16 * kb + tid4 * 2;
            const int col1 = col0 + 8;
            const uint32_t co0 = (uint32_t)((((col0 >> 3) ^ grp) << 4) + (col0 & 7) * 2);
            const uint32_t co1 = (uint32_t)((((col1 >> 3) ^ grp) << 4) + (col1 & 7) * 2);
            sts32(pbase + lr * 128 + co0,       h2u(__floats2half2_rn(e0, e1)));
            sts32(pbase + (lr + 8) * 128 + co0, h2u(__floats2half2_rn(e2, e3)));
            sts32(pbase + lr * 128 + co1,       h2u(__floats2half2_rn(e4, e5)));
            sts32(pbase + (lr + 8) * 128 + co1, h2u(__floats2half2_rn(e6, e7)));
        }
        // pair barrier: both warps' P written before either reads
        asm volatile("bar.sync %0, %1;" :: "r"(1 + aP), "r"(64) : "memory");

        // ---- O += P V: warp = 32 rows (pair) x 128 d-cols (half hP) ----
        #pragma unroll
        for (int kb = 0; kb < 4; kb++) {
            uint32_t pa0[4], pa1[4];
            ldsm4(pbase + rP * 128 + (((2 * kb + cP) ^ rxP) << 4), pa0);
            ldsm4(pbase + (16 + rP) * 128 + (((2 * kb + cP) ^ rxP) << 4), pa1);
            #pragma unroll
            for (int g = 0; g < 8; g++) {
                uint32_t v[4];
                ldsm4t(sVb + (16 * kb + rV) * 512
                           + (((16 * hP + 2 * g + cV) ^ rx) << 4), v);
                mma_f16(o[2 * g],          pa0, v[0], v[1]);
                mma_f16(o[2 * g + 1],      pa0, v[2], v[3]);
                mma_f16(o[16 + 2 * g],     pa1, v[0], v[1]);
                mma_f16(o[16 + 2 * g + 1], pa1, v[2], v[3]);
            }
        }
        __syncthreads();   // protect K/V stage before next tile's cp.async
    }

    // ---- l per QK row (complete over this unit's keys) -> Lbuf ----
    lsum0 += __shfl_xor_sync(0xffffffffu, lsum0, 1);
    lsum0 += __shfl_xor_sync(0xffffffffu, lsum0, 2);
    lsum1 += __shfl_xor_sync(0xffffffffu, lsum1, 1);
    lsum1 += __shfl_xor_sync(0xffffffffu, lsum1, 2);
    if (tid4 == 0) {
        LbufF[16 * w + grp]     = lsum0;
        LbufF[16 * w + grp + 8] = lsum1;
    }
    __syncthreads();

    if (kq < 3) {
        if (tid < 128) gLp[kq][qbase + tid] = LbufF[tid];
        #pragma unroll
        for (int m = 0; m < 2; m++) {
            const size_t row = qbase + 32 * aP + 16 * m + grp;
            #pragma unroll
            for (int j = 0; j < 16; j++) {
                const int col = 128 * hP + 8 * j + tid4 * 2;
                *(float2*)&gOp[kq][row * DD + col] =
                    make_float2(o[m * 16 + j][0], o[m * 16 + j][1]);
                *(float2*)&gOp[kq][(row + 8) * DD + col] =
                    make_float2(o[m * 16 + j][2], o[m * 16 + j][3]);
            }
        }
        __threadfence();
        __syncthreads();
        if (tid == 0) atomicAdd(&tileDone[tile], 1);
    } else {
        if (tid == 0) {
            spin_on(tileDone + tile, 3);
            __threadfence();
        }
        __syncthreads();

        #pragma unroll 1
        for (int m = 0; m < 2; m++) {
            const int lrow = 32 * aP + 16 * m + grp;
            const size_t row = qbase + lrow;
            float l0 = LbufF[lrow]     + gLp[0][row]     + gLp[1][row]     + gLp[2][row];
            float l1 = LbufF[lrow + 8] + gLp[0][row + 8] + gLp[1][row + 8] + gLp[2][row + 8];
            const float inv0 = 1.f / l0, inv1 = 1.f / l1;
            #pragma unroll
            for (int j = 0; j < 16; j++) {
                const int col = 128 * hP + 8 * j + tid4 * 2;
                const size_t i0 = row * DD + col;
                const size_t i1 = (row + 8) * DD + col;
                float2 a = make_float2(o[m * 16 + j][0], o[m * 16 + j][1]);
                float2 c = make_float2(o[m * 16 + j][2], o[m * 16 + j][3]);
                #pragma unroll
                for (int k = 0; k < 3; k++) {
                    float2 pa = *(const float2*)&gOp[k][i0];
                    float2 pc = *(const float2*)&gOp[k][i1];
                    a.x += pa.x; a.y += pa.y;
                    c.x += pc.x; c.y += pc.y;
                }
                *(float2*)(out + i0) = make_float2(a.x * inv0, a.y * inv0);
                *(float2*)(out + i1) = make_float2(c.x * inv1, c.y * inv1);
            }
        }
    }
}

// ---------------------------------------------------------------------------
extern "C" void kernel_launch(void* const* d_in, const int* in_sizes, int n_in,
                              void* d_out, int out_size)
{
    const float* x  = (const float*)d_in[0];
    const float* Wq = (const float*)d_in[1];
    const float* bq = (const float*)d_in[2];
    const float* Wk = (const float*)d_in[3];
    const float* bk = (const float*)d_in[4];
    const float* Wv = (const float*)d_in[5];
    const float* bv = (const float*)d_in[6];
    float* out = (float*)d_out;

    cudaFuncSetAttribute(mega, cudaFuncAttributeMaxDynamicSharedMemorySize,
                         MEGA_SMEM);

    convert_all<<<(NX4 + 3 * NW4 + 255) / 256, 256>>>(x, Wq, Wk, Wv);
    mega<<<768 + 1024, 256, MEGA_SMEM>>>(bq, bk, bv, out);
}

// round 11
// speedup vs baseline: 2.7213x; 2.6649x over previous
#include <cuda_runtime.h>
#include <cuda_fp16.h>
#include <cstdint>

#define BB   8
#define SS   4096
#define DIN  512
#define DD   256

// ---------------------------------------------------------------------------
// Global scratch (static __device__ arrays: no allocation)
// ---------------------------------------------------------------------------
__device__ __half gx[BB * SS * DIN];
__device__ __half gWq[DIN * DD], gWk[DIN * DD], gWv[DIN * DD];
__device__ __half gQ[BB * SS * DD], gK[BB * SS * DD], gV[BB * SS * DD];
__device__ float gOp[3][BB * SS * DD];   // O partials for k-quarters 0..2
__device__ float gLp[3][BB * SS];        // l partials
__device__ int   projDone[BB];           // per-batch proj completion counters
__device__ int   tileDone[256];          // per-qtile flash partial counters

// ---------------------------------------------------------------------------
// helpers
// ---------------------------------------------------------------------------
__device__ __forceinline__ uint32_t smem_u32(const void* p) {
    uint32_t a;
    asm("{ .reg .u64 t; cvta.to.shared.u64 t, %1; cvt.u32.u64 %0, t; }"
        : "=r"(a) : "l"(p));
    return a;
}
__device__ __forceinline__ void ldsm4(uint32_t a, uint32_t r[4]) {
    asm volatile("ldmatrix.sync.aligned.m8n8.x4.shared.b16 {%0,%1,%2,%3}, [%4];"
        : "=r"(r[0]), "=r"(r[1]), "=r"(r[2]), "=r"(r[3]) : "r"(a));
}
__device__ __forceinline__ void ldsm4t(uint32_t a, uint32_t r[4]) {
    asm volatile("ldmatrix.sync.aligned.m8n8.x4.trans.shared.b16 {%0,%1,%2,%3}, [%4];"
        : "=r"(r[0]), "=r"(r[1]), "=r"(r[2]), "=r"(r[3]) : "r"(a));
}
__device__ __forceinline__ void mma_f16(float c[4], const uint32_t a[4],
                                        uint32_t b0, uint32_t b1) {
    asm volatile(
        "mma.sync.aligned.m16n8k16.row.col.f32.f16.f16.f32 "
        "{%0,%1,%2,%3}, {%4,%5,%6,%7}, {%8,%9}, {%0,%1,%2,%3};"
        : "+f"(c[0]), "+f"(c[1]), "+f"(c[2]), "+f"(c[3])
        : "r"(a[0]), "r"(a[1]), "r"(a[2]), "r"(a[3]), "r"(b0), "r"(b1));
}
__device__ __forceinline__ float ex2(float x) {
    float r;
    asm("ex2.approx.f32 %0, %1;" : "=f"(r) : "f"(x));
    return r;
}
__device__ __forceinline__ uint32_t h2u(__half2 h) {
    return *reinterpret_cast<uint32_t*>(&h);
}
__device__ __forceinline__ void cpa16(uint32_t s, const void* g) {
    asm volatile("cp.async.cg.shared.global [%0], [%1], 16;" :: "r"(s), "l"(g));
}
#define CP_COMMIT() asm volatile("cp.async.commit_group;" ::: "memory")
#define CP_WAIT1()  asm volatile("cp.async.wait_group 1;" ::: "memory")
#define CP_WAIT0()  asm volatile("cp.async.wait_group 0;" ::: "memory")

__device__ __forceinline__ void spin_on(volatile int* ctr, int target) {
    while (*ctr < target) __nanosleep(128);
}

// ---------------------------------------------------------------------------
// Kernel 0: convert x + weights fp32->fp16, zero the flow counters.
// ---------------------------------------------------------------------------
#define NX4 (BB * SS * DIN / 4)
#define NW4 (DIN * DD / 4)

__global__ void convert_all(const float* __restrict__ x,
                            const float* __restrict__ Wq,
                            const float* __restrict__ Wk,
                            const float* __restrict__ Wv)
{
    if (blockIdx.x == 0) {
        int t = threadIdx.x;
        tileDone[t] = 0;
        if (t < BB) projDone[t] = 0;
    }
    int i = blockIdx.x * blockDim.x + threadIdx.x;
    const float* src;
    __half* dst;
    int idx;
    if (i < NX4) {
        src = x; dst = gx; idx = i;
    } else {
        int j = i - NX4;
        if (j >= 3 * NW4) return;
        int w = j / NW4;
        idx = j - w * NW4;
        src = (w == 0) ? Wq : (w == 1) ? Wk : Wv;
        dst = (w == 0) ? gWq : (w == 1) ? gWk : gWv;
    }
    float4 v = ((const float4*)src)[idx];
    __half2 a = __floats2half2_rn(v.x, v.y);
    __half2 b = __floats2half2_rn(v.z, v.w);
    ((uint2*)dst)[idx] = make_uint2(h2u(a), h2u(b));
}

// ---------------------------------------------------------------------------
// Fused mega-kernel. grid = 1792 CTAs, 256 thr, 192KB smem.
//   bid [0,768):      proj units, batch-major: b=bid/96, yb=(bid%96)/32, xt=bid%32
//   bid [768,1792):   flash units: fid=bid-768, kq=fid/256 (0..3), tile=fid%256
//                     tile -> b=tile/32, q0=(tile%32)*128; keys [kq*1024,(kq+1)*1024)
// Ordering guarantees every spinner waits only on lower-bid CTAs.
// ---------------------------------------------------------------------------
#define MEGA_SMEM 196608
// proj smem layout (within the 192KB)
#define PJ_W0     32768
#define PJ_XSTG   16384
#define PJ_WSTG   32768
// flash smem layout
#define FL_K0     65536
#define FL_V0     131072
#define FL_STG    32768

__device__ __forceinline__ void proj_issue(uint32_t sb, int st, int kb,
                                           const __half* xg, const __half* Wg,
                                           int tid)
{
    #pragma unroll
    for (int t = 0; t < 4; t++) {
        int idx = tid + t * 256;
        int r = idx >> 3, c = idx & 7;
        cpa16(sb + st * PJ_XSTG + (uint32_t)(r * 128 + ((c ^ (r & 7)) << 4)),
              xg + (size_t)r * DIN + kb * 64 + c * 8);
    }
    #pragma unroll
    for (int t = 0; t < 8; t++) {
        int idx = tid + t * 256;
        int r = idx >> 5, c = idx & 31;
        cpa16(sb + PJ_W0 + st * PJ_WSTG + (uint32_t)(r * 512 + ((c ^ (r & 7)) << 4)),
              Wg + (size_t)(kb * 64 + r) * DD + c * 8);
    }
    CP_COMMIT();
}

__device__ __forceinline__ void kv_issue_nc(uint32_t sb, int st,
                                            const __half* Kg, const __half* Vg,
                                            int tid)
{
    #pragma unroll
    for (int t = 0; t < 8; t++) {
        int idx = tid + t * 256;
        int r = idx >> 5, c = idx & 31;
        uint32_t off = (uint32_t)(r * 512 + ((c ^ (r & 7)) << 4));
        cpa16(sb + FL_K0 + st * FL_STG + off, Kg + (size_t)r * DD + c * 8);
        cpa16(sb + FL_V0 + st * FL_STG + off, Vg + (size_t)r * DD + c * 8);
    }
}

__global__ __launch_bounds__(256, 1) void mega(
    const float* __restrict__ bq, const float* __restrict__ bk,
    const float* __restrict__ bv, float* __restrict__ out)
{
    extern __shared__ char sm[];
    const uint32_t sb = smem_u32(sm);
    const int bid = blockIdx.x;
    const int tid = threadIdx.x;
    const int w   = tid >> 5;
    const int l   = tid & 31;
    const int grp = l >> 2, tid4 = l & 3;

    if (bid < 768) {
        // ==================== PROJ UNIT ====================
        const int bb = bid / 96;
        const int r96 = bid - bb * 96;
        const int yb = r96 >> 5;
        const int xt = r96 & 31;
        const int m0 = (bb * 32 + xt) * 128;

        const __half* W    = (yb == 0) ? gWq : (yb == 1) ? gWk : gWv;
        const float*  bias = (yb == 0) ? bq  : (yb == 1) ? bk  : bv;
        __half*       O    = (yb == 0) ? gQ  : (yb == 1) ? gK  : gV;
        const float scl = (yb == 0) ? 0.09014205f : 1.0f;  // log2(e)/16

        float o[32][4];
        #pragma unroll
        for (int i = 0; i < 32; i++)
            #pragma unroll
            for (int j = 0; j < 4; j++) o[i][j] = 0.f;

        const int rA  = w * 16 + (l & 15);
        const int cA  = l >> 4;
        const int rxA = rA & 7;
        const int rWb = (l & 7) + ((l >> 3) & 1) * 8;
        const int cW  = l >> 4;
        const int rxW = l & 7;

        const __half* xg = gx + (size_t)m0 * DIN;
        proj_issue(sb, 0, 0, xg, W, tid);

        #pragma unroll 1
        for (int kb = 0; kb < 8; kb++) {
            const int st = kb & 1;
            if (kb + 1 < 8) {
                proj_issue(sb, st ^ 1, kb + 1, xg, W, tid);
                CP_WAIT1();
            } else {
                CP_WAIT0();
            }
            __syncthreads();

            const uint32_t sX = sb + st * PJ_XSTG;
            const uint32_t sW = sb + PJ_W0 + st * PJ_WSTG;

            #pragma unroll
            for (int ks = 0; ks < 4; ks++) {
                uint32_t a[4];
                ldsm4(sX + rA * 128 + (((2 * ks + cA) ^ rxA) << 4), a);
                #pragma unroll
                for (int g = 0; g < 16; g++) {
                    uint32_t bfr[4];
                    ldsm4t(sW + (ks * 16 + rWb) * 512 + (((2 * g + cW) ^ rxW) << 4), bfr);
                    mma_f16(o[2 * g],     a, bfr[0], bfr[1]);
                    mma_f16(o[2 * g + 1], a, bfr[2], bfr[3]);
                }
            }
            __syncthreads();
        }

        const int r0 = m0 + w * 16 + grp;
        #pragma unroll
        for (int nf = 0; nf < 32; nf++) {
            int col = nf * 8 + tid4 * 2;
            float b0 = bias[col], b1 = bias[col + 1];
            __half2 h0 = __floats2half2_rn((o[nf][0] + b0) * scl, (o[nf][1] + b1) * scl);
            __half2 h1 = __floats2half2_rn((o[nf][2] + b0) * scl, (o[nf][3] + b1) * scl);
            *(uint32_t*)(O + (size_t)r0 * DD + col)       = h2u(h0);
            *(uint32_t*)(O + (size_t)(r0 + 8) * DD + col) = h2u(h1);
        }
        __threadfence();
        __syncthreads();
        if (tid == 0) atomicAdd(&projDone[bb], 1);
        return;
    }

    // ==================== FLASH UNIT (one k-quarter of one q-tile) ====
    const int fid  = bid - 768;
    const int kq   = fid >> 8;         // 0..3
    const int tile = fid & 255;
    const int b    = tile >> 5;
    const int q0   = (tile & 31) << 7;
    const size_t qbase = (size_t)b * SS + q0;
    const size_t kvb   = (size_t)b * SS;
    const int kt0 = kq * 16;           // 16 k-tiles of 64 keys each

    // wait for this batch's projection (producers all have lower bids)
    if (tid == 0) {
        spin_on(projDone + b, 96);
        __threadfence();
    }
    __syncthreads();

    // prologue: KV tile kt0 + Q tile in one cp.async group
    kv_issue_nc(sb, 0, gK + (kvb + kt0 * 64) * DD, gV + (kvb + kt0 * 64) * DD, tid);
    #pragma unroll
    for (int t = 0; t < 16; t++) {
        int idx = tid + t * 256;
        int r = idx >> 5, c = idx & 31;
        cpa16(sb + (uint32_t)(r * 512 + ((c ^ (r & 7)) << 4)),
              gQ + (qbase + r) * DD + c * 8);
    }
    CP_COMMIT();

    float o[32][4];
    #pragma unroll
    for (int i = 0; i < 32; i++)
        #pragma unroll
        for (int j = 0; j < 4; j++) o[i][j] = 0.f;
    float lsum0 = 0.f, lsum1 = 0.f;

    const int rA  = w * 16 + (l & 15);
    const int cA  = l >> 4;
    const int rxA = rA & 7;
    const uint32_t qrow = sb + rA * 512;
    const int rK  = ((l >> 4) << 3) + (l & 7);
    const int cK  = (l >> 3) & 1;
    const int rVb = (l & 7) + ((l >> 3) & 1) * 8;
    const int cV  = l >> 4;
    const int rx  = l & 7;

    #pragma unroll 1
    for (int kt = 0; kt < 16; kt++) {
        const int st = kt & 1;
        if (kt + 1 < 16) {
            kv_issue_nc(sb, st ^ 1, gK + (kvb + (kt0 + kt + 1) * 64) * DD,
                        gV + (kvb + (kt0 + kt + 1) * 64) * DD, tid);
            CP_COMMIT();
            CP_WAIT1();
        } else {
            CP_WAIT0();
        }
        __syncthreads();

        const uint32_t sKb = sb + FL_K0 + st * FL_STG;
        const uint32_t sVb = sb + FL_V0 + st * FL_STG;

        float s[8][4];
        #pragma unroll
        for (int i = 0; i < 8; i++)
            #pragma unroll
            for (int j = 0; j < 4; j++) s[i][j] = 0.f;

        #pragma unroll
        for (int ks = 0; ks < 16; ks++) {
            uint32_t a[4];
            ldsm4(qrow + (((2 * ks + cA) ^ rxA) << 4), a);
            #pragma unroll
            for (int h = 0; h < 4; h++) {
                uint32_t kh[4];
                ldsm4(sKb + (rK + h * 16) * 512 + (((2 * ks + cK) ^ rx) << 4), kh);
                mma_f16(s[2 * h],     a, kh[0], kh[1]);
                mma_f16(s[2 * h + 1], a, kh[2], kh[3]);
            }
        }

        uint32_t p[4][4];
        #pragma unroll
        for (int kb = 0; kb < 4; kb++) {
            float e0 = ex2(s[2 * kb][0]),     e1 = ex2(s[2 * kb][1]);
            float e2 = ex2(s[2 * kb][2]),     e3 = ex2(s[2 * kb][3]);
            float e4 = ex2(s[2 * kb + 1][0]), e5 = ex2(s[2 * kb + 1][1]);
            float e6 = ex2(s[2 * kb + 1][2]), e7 = ex2(s[2 * kb + 1][3]);
            __half2 q01 = __floats2half2_rn(e0, e1);
            __half2 q23 = __floats2half2_rn(e2, e3);
            __half2 q45 = __floats2half2_rn(e4, e5);
            __half2 q67 = __floats2half2_rn(e6, e7);
            p[kb][0] = h2u(q01);
            p[kb][1] = h2u(q23);
            p[kb][2] = h2u(q45);
            p[kb][3] = h2u(q67);
            float2 f01 = __half22float2(q01), f23 = __half22float2(q23);
            float2 f45 = __half22float2(q45), f67 = __half22float2(q67);
            lsum0 += (f01.x + f01.y) + (f45.x + f45.y);
            lsum1 += (f23.x + f23.y) + (f67.x + f67.y);
        }

        #pragma unroll
        for (int g = 0; g < 16; g++) {
            #pragma unroll
            for (int kb = 0; kb < 4; kb++) {
                uint32_t v[4];
                ldsm4t(sVb + (rVb + kb * 16) * 512 + (((2 * g + cV) ^ rx) << 4), v);
                mma_f16(o[2 * g],     p[kb], v[0], v[1]);
                mma_f16(o[2 * g + 1], p[kb], v[2], v[3]);
            }
        }
        __syncthreads();
    }

    // quad-reduce l partials
    lsum0 += __shfl_xor_sync(0xffffffffu, lsum0, 1);
    lsum0 += __shfl_xor_sync(0xffffffffu, lsum0, 2);
    lsum1 += __shfl_xor_sync(0xffffffffu, lsum1, 1);
    lsum1 += __shfl_xor_sync(0xffffffffu, lsum1, 2);

    const int r0g = (int)(qbase + w * 16 + grp);   // global row of first row

    if (kq < 3) {
        // store O partial + l partial
        #pragma unroll
        for (int nf = 0; nf < 32; nf++) {
            int col = nf * 8 + tid4 * 2;
            size_t i0 = (size_t)r0g * DD + col;
            size_t i1 = (size_t)(r0g + 8) * DD + col;
            *(float2*)&gOp[kq][i0] = make_float2(o[nf][0], o[nf][1]);
            *(float2*)&gOp[kq][i1] = make_float2(o[nf][2], o[nf][3]);
        }
        if (tid4 == 0) {
            gLp[kq][r0g]     = lsum0;
            gLp[kq][r0g + 8] = lsum1;
        }
        __threadfence();
        __syncthreads();
        if (tid == 0) atomicAdd(&tileDone[tile], 1);
    } else {
        // final unit: wait for peers (all lower bids), merge, normalize, store
        if (tid == 0) {
            spin_on(tileDone + tile, 3);
            __threadfence();
        }
        __syncthreads();

        float l0 = lsum0 + gLp[0][r0g]     + gLp[1][r0g]     + gLp[2][r0g];
        float l1 = lsum1 + gLp[0][r0g + 8] + gLp[1][r0g + 8] + gLp[2][r0g + 8];
        const float inv0 = 1.f / l0, inv1 = 1.f / l1;

        #pragma unroll
        for (int nf = 0; nf < 32; nf++) {
            int col = nf * 8 + tid4 * 2;
            size_t i0 = (size_t)r0g * DD + col;
            size_t i1 = (size_t)(r0g + 8) * DD + col;
            float2 a = make_float2(o[nf][0], o[nf][1]);
            float2 c = make_float2(o[nf][2], o[nf][3]);
            #pragma unroll
            for (int k = 0; k < 3; k++) {
                float2 pa = *(const float2*)&gOp[k][i0];
                float2 pc = *(const float2*)&gOp[k][i1];
                a.x += pa.x; a.y += pa.y;
                c.x += pc.x; c.y += pc.y;
            }
            *(float2*)(out + i0) = make_float2(a.x * inv0, a.y * inv0);
            *(float2*)(out + i1) = make_float2(c.x * inv1, c.y * inv1);
        }
    }
}

// ---------------------------------------------------------------------------
extern "C" void kernel_launch(void* const* d_in, const int* in_sizes, int n_in,
                              void* d_out, int out_size)
{
    const float* x  = (const float*)d_in[0];
    const float* Wq = (const float*)d_in[1];
    const float* bq = (const float*)d_in[2];
    const float* Wk = (const float*)d_in[3];
    const float* bk = (const float*)d_in[4];
    const float* Wv = (const float*)d_in[5];
    const float* bv = (const float*)d_in[6];
    float* out = (float*)d_out;

    cudaFuncSetAttribute(mega, cudaFuncAttributeMaxDynamicSharedMemorySize,
                         MEGA_SMEM);

    convert_all<<<(NX4 + 3 * NW4 + 255) / 256, 256>>>(x, Wq, Wk, Wv);
    mega<<<768 + 1024, 256, MEGA_SMEM>>>(bq, bk, bv, out);
}